// round 13
// baseline (speedup 1.0000x reference)
#include <cuda_runtime.h>
#include <cuda_bf16.h>
#include <cstdint>
#include <cstddef>

#define BB 131072

// ---------------- scratch (device globals) ----------------
__device__ int8_t g_z8h[(size_t)BB * 64];
__device__ int8_t g_z8l[(size_t)BB * 64];
__device__ int8_t g_w8h[40 * 4096];
__device__ int8_t g_w8l[40 * 4096];
__device__ int g_idx[BB];

// z scale 2^13, W scale 2^14 -> product scale 2^27
#define INV_SCALE 7.450580596923828e-9f

// ---------------- threefry2x32 (exact JAX rounds) ----------------
__device__ __forceinline__ uint32_t rotl32(uint32_t x, int d) { return (x << d) | (x >> (32 - d)); }
__device__ __forceinline__ void threefry2x32(uint32_t k0, uint32_t k1, uint32_t x0, uint32_t x1,
                                             uint32_t& o0, uint32_t& o1) {
    uint32_t ks0 = k0, ks1 = k1, ks2 = 0x1BD11BDAu ^ k0 ^ k1;
    x0 += ks0; x1 += ks1;
    x0 += x1; x1 = rotl32(x1, 13); x1 ^= x0;
    x0 += x1; x1 = rotl32(x1, 15); x1 ^= x0;
    x0 += x1; x1 = rotl32(x1, 26); x1 ^= x0;
    x0 += x1; x1 = rotl32(x1,  6); x1 ^= x0;
    x0 += ks1; x1 += ks2 + 1u;
    x0 += x1; x1 = rotl32(x1, 17); x1 ^= x0;
    x0 += x1; x1 = rotl32(x1, 29); x1 ^= x0;
    x0 += x1; x1 = rotl32(x1, 16); x1 ^= x0;
    x0 += x1; x1 = rotl32(x1, 24); x1 ^= x0;
    x0 += ks2; x1 += ks0 + 2u;
    x0 += x1; x1 = rotl32(x1, 13); x1 ^= x0;
    x0 += x1; x1 = rotl32(x1, 15); x1 ^= x0;
    x0 += x1; x1 = rotl32(x1, 26); x1 ^= x0;
    x0 += x1; x1 = rotl32(x1,  6); x1 ^= x0;
    x0 += ks0; x1 += ks1 + 3u;
    x0 += x1; x1 = rotl32(x1, 17); x1 ^= x0;
    x0 += x1; x1 = rotl32(x1, 29); x1 ^= x0;
    x0 += x1; x1 = rotl32(x1, 16); x1 ^= x0;
    x0 += x1; x1 = rotl32(x1, 24); x1 ^= x0;
    x0 += ks1; x1 += ks2 + 4u;
    x0 += x1; x1 = rotl32(x1, 13); x1 ^= x0;
    x0 += x1; x1 = rotl32(x1, 15); x1 ^= x0;
    x0 += x1; x1 = rotl32(x1, 26); x1 ^= x0;
    x0 += x1; x1 = rotl32(x1,  6); x1 ^= x0;
    x0 += ks2; x1 += ks0 + 5u;
    o0 = x0; o1 = x1;
}

// ---------------- PTX helpers (sm_80-level: safe on plain sm_103 target) ----------------
__device__ __forceinline__ uint32_t smem_u32(const void* p) {
    uint32_t a;
    asm("{ .reg .u64 t; cvta.to.shared.u64 t, %1; cvt.u32.u64 %0, t; }" : "=r"(a) : "l"(p));
    return a;
}
__device__ __forceinline__ void ldm_x4(uint32_t* r, uint32_t addr) {
    asm volatile("ldmatrix.sync.aligned.m8n8.x4.shared.b16 {%0,%1,%2,%3}, [%4];"
        : "=r"(r[0]), "=r"(r[1]), "=r"(r[2]), "=r"(r[3]) : "r"(addr));
}
__device__ __forceinline__ void mma16832s8(int* d, const uint32_t* a, const uint32_t* b) {
    asm volatile(
        "mma.sync.aligned.m16n8k32.row.col.s32.s8.s8.s32 "
        "{%0,%1,%2,%3}, {%4,%5,%6,%7}, {%8,%9}, {%0,%1,%2,%3};"
        : "+r"(d[0]), "+r"(d[1]), "+r"(d[2]), "+r"(d[3])
        : "r"(a[0]), "r"(a[1]), "r"(a[2]), "r"(a[3]), "r"(b[0]), "r"(b[1]));
}
__device__ __forceinline__ void cpasync16(uint32_t dst, const void* src) {
    asm volatile("cp.async.cg.shared.global [%0], [%1], 16;" :: "r"(dst), "l"(src));
}
#define CP_COMMIT() asm volatile("cp.async.commit_group;" ::: "memory")
#define CP_WAIT1()  asm volatile("cp.async.wait_group 1;" ::: "memory")

// split v (|v| <= 2^14) into hi/lo int8: v = 256*hi + lo
__device__ __forceinline__ void split16(int v, int& hi, int& lo) {
    hi = (v + 128) >> 8;
    lo = v - (hi << 8);
}

// ---------------- Kernel P: convert weights to int8 hi/lo (scale 2^14) ----------------
__global__ __launch_bounds__(256) void prep_w_kernel(const float* __restrict__ triz_w) {
    int t = blockIdx.x * 256 + threadIdx.x;
    if (t >= 40 * 4096) return;
    int wi = __float2int_rn(triz_w[t] * 16384.0f);
    int hi, lo;
    split16(wi, hi, lo);
    g_w8h[t] = (int8_t)hi;
    g_w8l[t] = (int8_t)lo;
}

// ---------------- Kernel A1: encoder + z(int8 hi/lo, scale 2^13) + raw policy logits ----------------
__global__ __launch_bounds__(128) void enc_kernel(
    const float* __restrict__ x, const float* __restrict__ enc_w,
    const float* __restrict__ enc_b, const float* __restrict__ pol_w,
    const float* __restrict__ pol_b, float* __restrict__ logits_out) {
    __shared__ float sew[320], seb[64], spw[2560], spb[40];
    int t = threadIdx.x;
    for (int i = t; i < 320; i += 128) sew[i] = enc_w[i];
    if (t < 64) seb[t] = enc_b[t];
    for (int i = t; i < 2560; i += 128) spw[i] = pol_w[i];
    if (t < 40) spb[t] = pol_b[t];
    __syncthreads();

    int b = blockIdx.x * 128 + t;
    float xv[5];
#pragma unroll
    for (int d = 0; d < 5; ++d) xv[d] = x[b * 5 + d];

    float z[64];
#pragma unroll
    for (int j = 0; j < 64; ++j) {
        float a = seb[j];
#pragma unroll
        for (int d = 0; d < 5; ++d) a = fmaf(xv[d], sew[j * 5 + d], a);
        z[j] = tanhf(a);
    }

    // quantize z -> int16 (scale 2^13), split into int8 hi/lo, pack + store
    uint4* zh = (uint4*)g_z8h + (size_t)b * 4;
    uint4* zl = (uint4*)g_z8l + (size_t)b * 4;
#pragma unroll
    for (int c = 0; c < 4; ++c) {
        uint32_t hq[4], lq[4];
#pragma unroll
        for (int q = 0; q < 4; ++q) {
            uint32_t hw = 0, lw = 0;
#pragma unroll
            for (int e = 0; e < 4; ++e) {
                int zi = __float2int_rn(z[c * 16 + q * 4 + e] * 8192.0f);
                int hi, lo;
                split16(zi, hi, lo);
                hw |= (uint32_t)(hi & 255) << (8 * e);
                lw |= (uint32_t)(lo & 255) << (8 * e);
            }
            hq[q] = hw;
            lq[q] = lw;
        }
        zh[c] = make_uint4(hq[0], hq[1], hq[2], hq[3]);
        zl[c] = make_uint4(lq[0], lq[1], lq[2], lq[3]);
    }

    float* lo_ = logits_out + (size_t)b * 40;
#pragma unroll 4
    for (int k = 0; k < 40; ++k) {
        float a = spb[k];
#pragma unroll
        for (int d = 0; d < 64; ++d) a = fmaf(z[d], spw[k * 64 + d], a);
        lo_[k] = a;
    }
}

// ---------------- Kernel A2: softmax + gumbel-argmax sample ----------------
__global__ __launch_bounds__(256) void sample_kernel(float* __restrict__ probs) {
    int b = blockIdx.x * 256 + threadIdx.x;
    float l[40];
    uint4* pp = (uint4*)(probs + (size_t)b * 40);
#pragma unroll
    for (int j = 0; j < 10; ++j) {
        uint4 v = pp[j];
        l[4 * j] = __uint_as_float(v.x); l[4 * j + 1] = __uint_as_float(v.y);
        l[4 * j + 2] = __uint_as_float(v.z); l[4 * j + 3] = __uint_as_float(v.w);
    }
    float m = -3.402823466e38f;
#pragma unroll
    for (int k = 0; k < 40; ++k) m = fmaxf(m, l[k]);
    float sum = 0.f;
#pragma unroll 4
    for (int k = 0; k < 40; ++k) {
        float e = expf(l[k] - m);
        l[k] = e;
        sum += e;
    }
    int best = 0;
    float bestv = -3.402823466e38f;
    const float TINY = 1.17549435e-38f;
#pragma unroll 4
    for (int k = 0; k < 40; ++k) {
        float p = l[k] / sum;
        l[k] = p;
        uint32_t i = (uint32_t)(b * 40 + k);
        uint32_t o0, o1;
        threefry2x32(0u, 1u, 0u, i, o0, o1);
        uint32_t bits = o0 ^ o1;
        float f = __uint_as_float((bits >> 9) | 0x3f800000u) - 1.0f;
        float u = fmaxf(f * (1.0f - TINY) + TINY, TINY);
        float g = -logf(-logf(u));
        float v = logf(p) + g;
        if (v > bestv) { bestv = v; best = k; }
    }
    g_idx[b] = best;
#pragma unroll
    for (int j = 0; j < 10; ++j)
        pp[j] = make_uint4(__float_as_uint(l[4 * j]), __float_as_uint(l[4 * j + 1]),
                           __float_as_uint(l[4 * j + 2]), __float_as_uint(l[4 * j + 3]));
}

// ---------------- Kernel B: TRIZ expert bank via int8 mma (exact 4-pass fixed point) ----------------
// CTA = 128 thr (4 warps) x 256 rows; m64 per warp. z,W int16 split into int8 hi/lo:
// z*w = 65536*zh*wh + 256*(zh*wl+zl*wh) + zl*wl, all passes exact in s32.
// mma.m16n8k32.s8 (4096 MACs/instr) -> 256 MMA/warp/expert (vs 384 bf16). k-chunks = 2.
// smem stride 80B (conflict-free ldmatrix), total 60.5KB -> 3 CTAs/SM.
#define ZROWS 256
#define ZT_B (ZROWS * 80)              /* 20480 B per z tile */
#define WMAT_B (64 * 80)               /* 5120 B per W matrix */
#define WBUF_STRIDE (2 * WMAT_B + 256) /* hi | lo | bias(64 f32) */
#define O_Z8H 0
#define O_Z8L ZT_B
#define O_WBUF (2 * ZT_B)
#define TRIZ_SMEM (O_WBUF + 2 * WBUF_STRIDE)

__global__ void __launch_bounds__(128, 3) triz_kernel(
    const float* __restrict__ triz_b, float* __restrict__ h_out) {
    extern __shared__ __align__(128) char sm[];
    uint32_t sb = smem_u32(sm);
    int t = threadIdx.x, wid = t >> 5, lane = t & 31;
    size_t row0 = (size_t)blockIdx.x * ZROWS;

    // prologue: z (hi+lo) -> group0 with W0 ; W1 -> group1
    {
        const uint4* zh = (const uint4*)(g_z8h + row0 * 64);
        const uint4* zl = (const uint4*)(g_z8l + row0 * 64);
#pragma unroll
        for (int i = 0; i < 8; ++i) {
            int c = t + i * 128;                 // chunk: row = c>>2, part = c&3
            uint32_t dst = sb + (c >> 2) * 80 + (c & 3) * 16;
            cpasync16(dst + O_Z8H, zh + c);
            cpasync16(dst + O_Z8L, zl + c);
        }
    }
    auto loadW = [&](int k, int p) {             // 256 chunks per matrix + bias
        if (k >= 40) return;
        const uint4* sh = (const uint4*)(g_w8h + (size_t)k * 4096);
        const uint4* sl = (const uint4*)(g_w8l + (size_t)k * 4096);
        uint32_t base = sb + O_WBUF + p * WBUF_STRIDE;
#pragma unroll
        for (int i = 0; i < 2; ++i) {
            int c = t + i * 128;
            uint32_t dst = base + (c >> 2) * 80 + (c & 3) * 16;
            cpasync16(dst, sh + c);
            cpasync16(dst + WMAT_B, sl + c);
        }
        if (t < 16) cpasync16(base + 2 * WMAT_B + t * 16,
                              (const uint4*)(triz_b + k * 64) + t);
    };
    loadW(0, 0);
    CP_COMMIT();
    loadW(1, 1);
    CP_COMMIT();

    CP_WAIT1();                                  // z + W0 ready
    __syncthreads();

    // A fragments, loop-invariant: 4 m16 sets per warp, 2 k-chunks (k32 each)
    uint32_t azh[4][2][4], azl[4][2][4];
    {
        int lr = lane & 7, sel = lane >> 3;
        int colb = (sel >> 1) * 16;              // 0 or 16 bytes
#pragma unroll
        for (int s = 0; s < 4; ++s) {
            int row = wid * 64 + s * 16 + ((sel & 1) << 3) + lr;
            uint32_t base = sb + row * 80 + colb;
#pragma unroll
            for (int kc = 0; kc < 2; ++kc) {
                ldm_x4(azh[s][kc], base + O_Z8H + kc * 32);
                ldm_x4(azl[s][kc], base + O_Z8L + kc * 32);
            }
        }
    }

    int gid = lane >> 2, tig = lane & 3;
    // B ldm_x4 lane offset: groups 0,1 -> W_hi (16B halves of k32), groups 2,3 -> W_lo
    int lr = lane & 7, grp = lane >> 3;
    uint32_t off_lane = (uint32_t)(lr * 80 + (grp & 1) * 16 + (grp >> 1) * WMAT_B);
    size_t rA = row0 + wid * 64 + gid;           // set s rows: rA + s*16, rA + s*16 + 8

    for (int k = 0; k < 40; ++k) {
        int p = k & 1;
        if (k > 0) {
            CP_WAIT1();
            __syncthreads();
        }
        uint32_t wb = sb + O_WBUF + p * WBUF_STRIDE + off_lane;
        const float* bias_sm = (const float*)(sm + O_WBUF + p * WBUF_STRIDE + 2 * WMAT_B);

#pragma unroll
        for (int nt = 0; nt < 8; ++nt) {
            float2 bv = *(const float2*)(bias_sm + nt * 8 + 2 * tig);
            int hh[4][4], md[4][4], ll[4][4];
#pragma unroll
            for (int s = 0; s < 4; ++s)
#pragma unroll
                for (int j = 0; j < 4; ++j) { hh[s][j] = 0; md[s][j] = 0; ll[s][j] = 0; }
            uint32_t nb = wb + nt * 640;         // 8 rows * 80B
#pragma unroll
            for (int kc = 0; kc < 2; ++kc) {
                uint32_t bf[4];                  // bf[0..1]=W_hi frag, bf[2..3]=W_lo frag
                ldm_x4(bf, nb + kc * 32);
#pragma unroll
                for (int s = 0; s < 4; ++s) {
                    mma16832s8(hh[s], azh[s][kc], bf);       // zh*wh
                    mma16832s8(md[s], azl[s][kc], bf);       // zl*wh
                    mma16832s8(md[s], azh[s][kc], bf + 2);   // zh*wl
                    mma16832s8(ll[s], azl[s][kc], bf + 2);   // zl*wl
                }
            }
            size_t cof = (size_t)k * 64 + nt * 8 + 2 * tig;
#pragma unroll
            for (int s = 0; s < 4; ++s) {
                float c0 = (float)hh[s][0] * 65536.f + ((float)md[s][0] * 256.f + (float)ll[s][0]);
                float c1 = (float)hh[s][1] * 65536.f + ((float)md[s][1] * 256.f + (float)ll[s][1]);
                float c2 = (float)hh[s][2] * 65536.f + ((float)md[s][2] * 256.f + (float)ll[s][2]);
                float c3 = (float)hh[s][3] * 65536.f + ((float)md[s][3] * 256.f + (float)ll[s][3]);
                size_t r = rA + s * 16;
                *(float2*)(h_out + r * 2560 + cof) = make_float2(
                    fmaxf(fmaf(c0, INV_SCALE, bv.x), 0.f),
                    fmaxf(fmaf(c1, INV_SCALE, bv.y), 0.f));
                *(float2*)(h_out + (r + 8) * 2560 + cof) = make_float2(
                    fmaxf(fmaf(c2, INV_SCALE, bv.x), 0.f),
                    fmaxf(fmaf(c3, INV_SCALE, bv.y), 0.f));
            }
        }
        __syncthreads();                         // done reading buf p before refill
        loadW(k + 2, p);                         // prefetch into freed parity buffer
        CP_COMMIT();                             // uniform group accounting
    }
}

// ---------------- Kernel C: gather selected expert + decoder ----------------
__global__ __launch_bounds__(256) void decode_kernel(
    const float* __restrict__ dec_w, const float* __restrict__ dec_b,
    const float* __restrict__ h, float* __restrict__ out) {
    int b = blockIdx.x * 256 + threadIdx.x;
    int k = g_idx[b];
    const float4* hp = (const float4*)(h + ((size_t)b * 40 + k) * 64);
    float acc[5];
#pragma unroll
    for (int j = 0; j < 5; ++j) acc[j] = dec_b[j];
#pragma unroll
    for (int i = 0; i < 16; ++i) {
        float4 v = hp[i];
        int d = i * 4;
#pragma unroll
        for (int j = 0; j < 5; ++j) {
            acc[j] = fmaf(v.x, dec_w[j * 64 + d],     acc[j]);
            acc[j] = fmaf(v.y, dec_w[j * 64 + d + 1], acc[j]);
            acc[j] = fmaf(v.z, dec_w[j * 64 + d + 2], acc[j]);
            acc[j] = fmaf(v.w, dec_w[j * 64 + d + 3], acc[j]);
        }
    }
#pragma unroll
    for (int j = 0; j < 5; ++j) out[b * 5 + j] = acc[j];
}

// ---------------- launch ----------------
extern "C" void kernel_launch(void* const* d_in, const int* in_sizes, int n_in,
                              void* d_out, int out_size) {
    const float* x      = (const float*)d_in[0];
    const float* enc_w  = (const float*)d_in[1];
    const float* enc_b  = (const float*)d_in[2];
    const float* triz_w = (const float*)d_in[3];
    const float* triz_b = (const float*)d_in[4];
    const float* pol_w  = (const float*)d_in[5];
    const float* pol_b  = (const float*)d_in[6];
    const float* dec_w  = (const float*)d_in[7];
    const float* dec_b  = (const float*)d_in[8];

    float* out   = (float*)d_out;                 // [B,5]
    float* probs = out + (size_t)BB * 5;          // [B,40]
    float* h     = out + (size_t)BB * 45;         // [B,40,64]

    cudaFuncSetAttribute(triz_kernel, cudaFuncAttributeMaxDynamicSharedMemorySize, TRIZ_SMEM);

    prep_w_kernel<<<(40 * 4096 + 255) / 256, 256>>>(triz_w);
    enc_kernel<<<BB / 128, 128>>>(x, enc_w, enc_b, pol_w, pol_b, probs);
    sample_kernel<<<BB / 256, 256>>>(probs);
    triz_kernel<<<BB / 256, 128, TRIZ_SMEM>>>(triz_b, h);
    decode_kernel<<<BB / 256, 256>>>(dec_w, dec_b, h, out);
}

// round 16
// speedup vs baseline: 5.4694x; 5.4694x over previous
#include <cuda_runtime.h>
#include <cuda_fp16.h>
#include <cstdint>
#include <cstddef>

#define BB 131072

// ---------------- scratch (device globals) ----------------
__device__ __half g_zf[(size_t)BB * 64];
__device__ __half g_wfh[40 * 4096];
__device__ __half g_wfl[40 * 4096];
__device__ int g_idx[BB];

// ---------------- threefry2x32 (exact JAX rounds) ----------------
__device__ __forceinline__ uint32_t rotl32(uint32_t x, int d) { return (x << d) | (x >> (32 - d)); }
__device__ __forceinline__ void threefry2x32(uint32_t k0, uint32_t k1, uint32_t x0, uint32_t x1,
                                             uint32_t& o0, uint32_t& o1) {
    uint32_t ks0 = k0, ks1 = k1, ks2 = 0x1BD11BDAu ^ k0 ^ k1;
    x0 += ks0; x1 += ks1;
    x0 += x1; x1 = rotl32(x1, 13); x1 ^= x0;
    x0 += x1; x1 = rotl32(x1, 15); x1 ^= x0;
    x0 += x1; x1 = rotl32(x1, 26); x1 ^= x0;
    x0 += x1; x1 = rotl32(x1,  6); x1 ^= x0;
    x0 += ks1; x1 += ks2 + 1u;
    x0 += x1; x1 = rotl32(x1, 17); x1 ^= x0;
    x0 += x1; x1 = rotl32(x1, 29); x1 ^= x0;
    x0 += x1; x1 = rotl32(x1, 16); x1 ^= x0;
    x0 += x1; x1 = rotl32(x1, 24); x1 ^= x0;
    x0 += ks2; x1 += ks0 + 2u;
    x0 += x1; x1 = rotl32(x1, 13); x1 ^= x0;
    x0 += x1; x1 = rotl32(x1, 15); x1 ^= x0;
    x0 += x1; x1 = rotl32(x1, 26); x1 ^= x0;
    x0 += x1; x1 = rotl32(x1,  6); x1 ^= x0;
    x0 += ks0; x1 += ks1 + 3u;
    x0 += x1; x1 = rotl32(x1, 17); x1 ^= x0;
    x0 += x1; x1 = rotl32(x1, 29); x1 ^= x0;
    x0 += x1; x1 = rotl32(x1, 16); x1 ^= x0;
    x0 += x1; x1 = rotl32(x1, 24); x1 ^= x0;
    x0 += ks1; x1 += ks2 + 4u;
    x0 += x1; x1 = rotl32(x1, 13); x1 ^= x0;
    x0 += x1; x1 = rotl32(x1, 15); x1 ^= x0;
    x0 += x1; x1 = rotl32(x1, 26); x1 ^= x0;
    x0 += x1; x1 = rotl32(x1,  6); x1 ^= x0;
    x0 += ks2; x1 += ks0 + 5u;
    o0 = x0; o1 = x1;
}

// ---------------- PTX helpers (sm_80-level: safe on plain sm_103 target) ----------------
__device__ __forceinline__ uint32_t smem_u32(const void* p) {
    uint32_t a;
    asm("{ .reg .u64 t; cvta.to.shared.u64 t, %1; cvt.u32.u64 %0, t; }" : "=r"(a) : "l"(p));
    return a;
}
__device__ __forceinline__ void ldm_x4(uint32_t* r, uint32_t addr) {
    asm volatile("ldmatrix.sync.aligned.m8n8.x4.shared.b16 {%0,%1,%2,%3}, [%4];"
        : "=r"(r[0]), "=r"(r[1]), "=r"(r[2]), "=r"(r[3]) : "r"(addr));
}
__device__ __forceinline__ void mma16816h(float* d, const uint32_t* a, const uint32_t* b) {
    asm volatile(
        "mma.sync.aligned.m16n8k16.row.col.f32.f16.f16.f32 "
        "{%0,%1,%2,%3}, {%4,%5,%6,%7}, {%8,%9}, {%0,%1,%2,%3};"
        : "+f"(d[0]), "+f"(d[1]), "+f"(d[2]), "+f"(d[3])
        : "r"(a[0]), "r"(a[1]), "r"(a[2]), "r"(a[3]), "r"(b[0]), "r"(b[1]));
}
__device__ __forceinline__ void cpasync16(uint32_t dst, const void* src) {
    asm volatile("cp.async.cg.shared.global [%0], [%1], 16;" :: "r"(dst), "l"(src));
}
#define CP_COMMIT() asm volatile("cp.async.commit_group;" ::: "memory")
#define CP_WAIT1()  asm volatile("cp.async.wait_group 1;" ::: "memory")

// ---------------- Kernel P: split weights into fp16 hi/lo (exact: w = wh + wl + O(2^-22)) ----------------
__global__ __launch_bounds__(256) void prep_w_kernel(const float* __restrict__ triz_w) {
    int t = blockIdx.x * 256 + threadIdx.x;
    if (t >= 40 * 4096) return;
    float v = triz_w[t];
    __half hi = __float2half_rn(v);
    __half lo = __float2half_rn(v - __half2float(hi));
    g_wfh[t] = hi;
    g_wfl[t] = lo;
}

// ---------------- Kernel A1: encoder + z(fp16) + raw policy logits ----------------
__global__ __launch_bounds__(128) void enc_kernel(
    const float* __restrict__ x, const float* __restrict__ enc_w,
    const float* __restrict__ enc_b, const float* __restrict__ pol_w,
    const float* __restrict__ pol_b, float* __restrict__ logits_out) {
    __shared__ float sew[320], seb[64], spw[2560], spb[40];
    int t = threadIdx.x;
    for (int i = t; i < 320; i += 128) sew[i] = enc_w[i];
    if (t < 64) seb[t] = enc_b[t];
    for (int i = t; i < 2560; i += 128) spw[i] = pol_w[i];
    if (t < 40) spb[t] = pol_b[t];
    __syncthreads();

    int b = blockIdx.x * 128 + t;
    float xv[5];
#pragma unroll
    for (int d = 0; d < 5; ++d) xv[d] = x[b * 5 + d];

    float z[64];
#pragma unroll
    for (int j = 0; j < 64; ++j) {
        float a = seb[j];
#pragma unroll
        for (int d = 0; d < 5; ++d) a = fmaf(xv[d], sew[j * 5 + d], a);
        z[j] = tanhf(a);
    }

    // store z as fp16 (single matrix)
    uint4* zo = (uint4*)g_zf + (size_t)b * 8;
#pragma unroll
    for (int c = 0; c < 8; ++c) {
        uint32_t q[4];
#pragma unroll
        for (int e = 0; e < 4; ++e) {
            __half2 hv = __floats2half2_rn(z[c * 8 + 2 * e], z[c * 8 + 2 * e + 1]);
            q[e] = *(uint32_t*)&hv;
        }
        zo[c] = make_uint4(q[0], q[1], q[2], q[3]);
    }

    float* lo_ = logits_out + (size_t)b * 40;
#pragma unroll 4
    for (int k = 0; k < 40; ++k) {
        float a = spb[k];
#pragma unroll
        for (int d = 0; d < 64; ++d) a = fmaf(z[d], spw[k * 64 + d], a);
        lo_[k] = a;
    }
}

// ---------------- Kernel A2: softmax + gumbel-argmax sample ----------------
__global__ __launch_bounds__(256) void sample_kernel(float* __restrict__ probs) {
    int b = blockIdx.x * 256 + threadIdx.x;
    float l[40];
    uint4* pp = (uint4*)(probs + (size_t)b * 40);
#pragma unroll
    for (int j = 0; j < 10; ++j) {
        uint4 v = pp[j];
        l[4 * j] = __uint_as_float(v.x); l[4 * j + 1] = __uint_as_float(v.y);
        l[4 * j + 2] = __uint_as_float(v.z); l[4 * j + 3] = __uint_as_float(v.w);
    }
    float m = -3.402823466e38f;
#pragma unroll
    for (int k = 0; k < 40; ++k) m = fmaxf(m, l[k]);
    float sum = 0.f;
#pragma unroll 4
    for (int k = 0; k < 40; ++k) {
        float e = expf(l[k] - m);
        l[k] = e;
        sum += e;
    }
    int best = 0;
    float bestv = -3.402823466e38f;
    const float TINY = 1.17549435e-38f;
#pragma unroll 4
    for (int k = 0; k < 40; ++k) {
        float p = l[k] / sum;
        l[k] = p;
        uint32_t i = (uint32_t)(b * 40 + k);
        uint32_t o0, o1;
        threefry2x32(0u, 1u, 0u, i, o0, o1);
        uint32_t bits = o0 ^ o1;
        float f = __uint_as_float((bits >> 9) | 0x3f800000u) - 1.0f;
        float u = fmaxf(f * (1.0f - TINY) + TINY, TINY);
        float g = -logf(-logf(u));
        float v = logf(p) + g;
        if (v > bestv) { bestv = v; best = k; }
    }
    g_idx[b] = best;
#pragma unroll
    for (int j = 0; j < 10; ++j)
        pp[j] = make_uint4(__float_as_uint(l[4 * j]), __float_as_uint(l[4 * j + 1]),
                           __float_as_uint(l[4 * j + 2]), __float_as_uint(l[4 * j + 3]));
}

// ---------------- Kernel B: TRIZ expert bank via mma.sync fp16 (W-split 2-pass) ----------------
// CTA = 128 thr (4 warps) x 256 rows; m64 per warp. h = z_f16*(wh + wl): 2 HMMA passes
// (vs 3 for bf16 hi/lo) -> 256 MMA/warp/expert. z single fp16 smem matrix; W hi/lo + bias
// double-buffered via cp.async. B hi+lo fetched in ONE ldm_x4. smem 72.5KB -> 3 CTAs/SM.
#define ZROWS 256
#define ZT_B (ZROWS * 144)             /* 36864 B z tile (stride 144B, conflict-free) */
#define WMAT_B (64 * 144)              /* 9216 B per W matrix */
#define WBUF_STRIDE (2 * WMAT_B + 256) /* hi | lo | bias(64 f32) */
#define O_WBUF ZT_B
#define TRIZ_SMEM (O_WBUF + 2 * WBUF_STRIDE)

__global__ void __launch_bounds__(128, 3) triz_kernel(
    const float* __restrict__ triz_b, float* __restrict__ h_out) {
    extern __shared__ __align__(128) char sm[];
    uint32_t sb = smem_u32(sm);
    int t = threadIdx.x, wid = t >> 5, lane = t & 31;
    size_t row0 = (size_t)blockIdx.x * ZROWS;

    // prologue: z -> group0 with W0 ; W1 -> group1
    {
        const uint4* zg = (const uint4*)(g_zf + row0 * 64);
#pragma unroll
        for (int i = 0; i < 16; ++i) {
            int c = t + i * 128;                 // chunk: row = c>>3, part = c&7
            cpasync16(sb + (c >> 3) * 144 + (c & 7) * 16, zg + c);
        }
    }
    auto loadW = [&](int k, int p) {             // 512 chunks per matrix + bias
        if (k >= 40) return;
        const uint4* sh = (const uint4*)(g_wfh + (size_t)k * 4096);
        const uint4* sl = (const uint4*)(g_wfl + (size_t)k * 4096);
        uint32_t base = sb + O_WBUF + p * WBUF_STRIDE;
#pragma unroll
        for (int i = 0; i < 4; ++i) {
            int c = t + i * 128;
            uint32_t dst = base + (c >> 3) * 144 + (c & 7) * 16;
            cpasync16(dst, sh + c);
            cpasync16(dst + WMAT_B, sl + c);
        }
        if (t < 16) cpasync16(base + 2 * WMAT_B + t * 16,
                              (const uint4*)(triz_b + k * 64) + t);
    };
    loadW(0, 0);
    CP_COMMIT();
    loadW(1, 1);
    CP_COMMIT();

    CP_WAIT1();                                  // z + W0 ready
    __syncthreads();

    // A fragments, loop-invariant: 4 m16 sets per warp, 4 k-chunks (k16 each)
    uint32_t az[4][4][4];
    {
        int lr = lane & 7, sel = lane >> 3;
        int kof = (sel & 2) << 2;                // 0 or 8 elems (16B)
#pragma unroll
        for (int s = 0; s < 4; ++s) {
            int row = wid * 64 + s * 16 + ((sel & 1) << 3) + lr;
            uint32_t base = sb + row * 144 + kof * 2;
#pragma unroll
            for (int kc = 0; kc < 4; ++kc) ldm_x4(az[s][kc], base + kc * 32);
        }
    }

    int gid = lane >> 2, tig = lane & 3;
    // B ldm_x4 lane offset: groups 0,1 -> W_hi (k-lo/k-hi 16B), groups 2,3 -> W_lo
    int lr = lane & 7, grp = lane >> 3;
    uint32_t off_lane = (uint32_t)(lr * 144 + (grp & 1) * 16 + (grp >> 1) * WMAT_B);
    size_t rA = row0 + wid * 64 + gid;           // set s rows: rA + s*16, rA + s*16 + 8

    for (int k = 0; k < 40; ++k) {
        int p = k & 1;
        if (k > 0) {
            CP_WAIT1();
            __syncthreads();
        }
        uint32_t wb = sb + O_WBUF + p * WBUF_STRIDE + off_lane;
        const float* bias_sm = (const float*)(sm + O_WBUF + p * WBUF_STRIDE + 2 * WMAT_B);

#pragma unroll
        for (int nt = 0; nt < 8; ++nt) {
            float2 bv = *(const float2*)(bias_sm + nt * 8 + 2 * tig);
            float acca[4][4], accb[4][4];
#pragma unroll
            for (int s = 0; s < 4; ++s) {
                acca[s][0] = 0.f; acca[s][1] = 0.f; acca[s][2] = 0.f; acca[s][3] = 0.f;
                accb[s][0] = 0.f; accb[s][1] = 0.f; accb[s][2] = 0.f; accb[s][3] = 0.f;
            }
            uint32_t nb = wb + nt * 1152;        // 8 rows * 144B
#pragma unroll
            for (int kc = 0; kc < 4; ++kc) {
                uint32_t bf[4];                  // bf[0..1]=W_hi frag, bf[2..3]=W_lo frag
                ldm_x4(bf, nb + kc * 32);
#pragma unroll
                for (int s = 0; s < 4; ++s) {
                    mma16816h(acca[s], az[s][kc], bf);       // z * wh
                    mma16816h(accb[s], az[s][kc], bf + 2);   // z * wl
                }
            }
            size_t cof = (size_t)k * 64 + nt * 8 + 2 * tig;
#pragma unroll
            for (int s = 0; s < 4; ++s) {
                size_t r = rA + s * 16;
                *(float2*)(h_out + r * 2560 + cof) = make_float2(
                    fmaxf(acca[s][0] + accb[s][0] + bv.x, 0.f),
                    fmaxf(acca[s][1] + accb[s][1] + bv.y, 0.f));
                *(float2*)(h_out + (r + 8) * 2560 + cof) = make_float2(
                    fmaxf(acca[s][2] + accb[s][2] + bv.x, 0.f),
                    fmaxf(acca[s][3] + accb[s][3] + bv.y, 0.f));
            }
        }
        __syncthreads();                         // done reading buf p before refill
        loadW(k + 2, p);                         // prefetch into freed parity buffer
        CP_COMMIT();                             // uniform group accounting
    }
}

// ---------------- Kernel C: gather selected expert + decoder ----------------
__global__ __launch_bounds__(256) void decode_kernel(
    const float* __restrict__ dec_w, const float* __restrict__ dec_b,
    const float* __restrict__ h, float* __restrict__ out) {
    int b = blockIdx.x * 256 + threadIdx.x;
    int k = g_idx[b];
    const float4* hp = (const float4*)(h + ((size_t)b * 40 + k) * 64);
    float acc[5];
#pragma unroll
    for (int j = 0; j < 5; ++j) acc[j] = dec_b[j];
#pragma unroll
    for (int i = 0; i < 16; ++i) {
        float4 v = hp[i];
        int d = i * 4;
#pragma unroll
        for (int j = 0; j < 5; ++j) {
            acc[j] = fmaf(v.x, dec_w[j * 64 + d],     acc[j]);
            acc[j] = fmaf(v.y, dec_w[j * 64 + d + 1], acc[j]);
            acc[j] = fmaf(v.z, dec_w[j * 64 + d + 2], acc[j]);
            acc[j] = fmaf(v.w, dec_w[j * 64 + d + 3], acc[j]);
        }
    }
#pragma unroll
    for (int j = 0; j < 5; ++j) out[b * 5 + j] = acc[j];
}

// ---------------- launch ----------------
extern "C" void kernel_launch(void* const* d_in, const int* in_sizes, int n_in,
                              void* d_out, int out_size) {
    const float* x      = (const float*)d_in[0];
    const float* enc_w  = (const float*)d_in[1];
    const float* enc_b  = (const float*)d_in[2];
    const float* triz_w = (const float*)d_in[3];
    const float* triz_b = (const float*)d_in[4];
    const float* pol_w  = (const float*)d_in[5];
    const float* pol_b  = (const float*)d_in[6];
    const float* dec_w  = (const float*)d_in[7];
    const float* dec_b  = (const float*)d_in[8];

    float* out   = (float*)d_out;                 // [B,5]
    float* probs = out + (size_t)BB * 5;          // [B,40]
    float* h     = out + (size_t)BB * 45;         // [B,40,64]

    cudaFuncSetAttribute(triz_kernel, cudaFuncAttributeMaxDynamicSharedMemorySize, TRIZ_SMEM);

    prep_w_kernel<<<(40 * 4096 + 255) / 256, 256>>>(triz_w);
    enc_kernel<<<BB / 128, 128>>>(x, enc_w, enc_b, pol_w, pol_b, probs);
    sample_kernel<<<BB / 256, 256>>>(probs);
    triz_kernel<<<BB / 256, 128, TRIZ_SMEM>>>(triz_b, h);
    decode_kernel<<<BB / 256, 256>>>(dec_w, dec_b, h, out);
}